// round 2
// baseline (speedup 1.0000x reference)
#include <cuda_runtime.h>
#include <math.h>

#define H_IMG 200
#define W_IMG 200
#define HW    40000
#define C1    64
#define C3    256
#define NHEADS 8
#define HD    32
#define BSZ   2
#define CF    1024
#define ATT_SCALE 0.17677669529663687f   // 32^-0.5

// ---------------- static scratch (no allocations allowed) ----------------
__device__ float g_Q  [BSZ * C3 * HW];   // (B, 256, H, W)
__device__ float g_K  [BSZ * C3 * HW];
__device__ float g_V  [BSZ * C3 * HW];
__device__ float g_AO [BSZ * C3 * HW];   // attention output, NCHW
__device__ float g_X  [BSZ * HW * C3];   // NHWC
__device__ float g_Y  [BSZ * HW * C3];   // NHWC
__device__ float g_Hid[BSZ * HW * CF];   // FFN hidden, (N_pix, 1024)

// ---------------- generic fp32 tiled GEMM: C = A(MxK) * B(KxN) ----------------
// A row-major [M,K], B row-major [K,N].
// TRANS_OUT: C stored as [N,M] (ldc=M)  -> used to emit NHWC directly.
// ACC: C += result. RELU / HAS_BIAS: fused epilogue (bias indexed by n).
template<bool TRANS_OUT, bool ACC, bool RELU, bool HAS_BIAS>
__global__ __launch_bounds__(256) void gemm128(
    const float* __restrict__ A, const float* __restrict__ B,
    const float* __restrict__ bias, float* __restrict__ C,
    int M, int N, int Kd, long aStr, long bStr, long cStr)
{
    __shared__ float As[8][128];
    __shared__ float Bs[8][128];
    A += (long)blockIdx.z * aStr;
    B += (long)blockIdx.z * bStr;
    C += (long)blockIdx.z * cStr;

    const int m0 = blockIdx.y * 128;
    const int n0 = blockIdx.x * 128;
    const int t  = threadIdx.x;
    const int ty = t >> 4, tx = t & 15;          // 16x16 threads, 8x8 microtile
    const int arow = t >> 1,  acol = (t & 1) * 4;   // A tile 128x8
    const int brow = t >> 5,  bcol = (t & 31) * 4;  // B tile 8x128
    const bool bok = (n0 + bcol) < N;            // N-edge guard (M,K always divisible)

    float acc[8][8];
#pragma unroll
    for (int i = 0; i < 8; i++)
#pragma unroll
        for (int j = 0; j < 8; j++) acc[i][j] = 0.f;

    for (int k0 = 0; k0 < Kd; k0 += 8) {
        float4 av = *(const float4*)(A + (long)(m0 + arow) * Kd + k0 + acol);
        float4 bv = make_float4(0.f, 0.f, 0.f, 0.f);
        if (bok) bv = *(const float4*)(B + (long)(k0 + brow) * N + n0 + bcol);

        As[acol + 0][arow] = av.x;
        As[acol + 1][arow] = av.y;
        As[acol + 2][arow] = av.z;
        As[acol + 3][arow] = av.w;
        *(float4*)&Bs[brow][bcol] = bv;
        __syncthreads();

#pragma unroll
        for (int k = 0; k < 8; k++) {
            float af[8], bf[8];
            *(float4*)&af[0] = *(const float4*)&As[k][ty * 8];
            *(float4*)&af[4] = *(const float4*)&As[k][ty * 8 + 4];
            *(float4*)&bf[0] = *(const float4*)&Bs[k][tx * 8];
            *(float4*)&bf[4] = *(const float4*)&Bs[k][tx * 8 + 4];
#pragma unroll
            for (int i = 0; i < 8; i++)
#pragma unroll
                for (int j = 0; j < 8; j++)
                    acc[i][j] += af[i] * bf[j];
        }
        __syncthreads();
    }

#pragma unroll
    for (int i = 0; i < 8; i++) {
        int m = m0 + ty * 8 + i;
#pragma unroll
        for (int j = 0; j < 8; j++) {
            int n = n0 + tx * 8 + j;
            if (n < N) {
                float v = acc[i][j];
                if (HAS_BIAS) v += bias[n];
                if (RELU)     v = fmaxf(v, 0.f);
                long idx = TRANS_OUT ? (long)n * M + m : (long)m * N + n;
                if (ACC) v += C[idx];
                C[idx] = v;
            }
        }
    }
}

// ---------------- 7x7 local-window attention, replicate padding ----------------
// one thread = one (pixel, head); online softmax; Q/acc in registers.
__global__ __launch_bounds__(256) void attn_kernel(
    const float* __restrict__ Q, const float* __restrict__ K,
    const float* __restrict__ V, float* __restrict__ O)
{
    const int b = blockIdx.z, nh = blockIdx.y;
    const int hw = blockIdx.x * blockDim.x + threadIdx.x;
    if (hw >= HW) return;
    const int h = hw / W_IMG, w = hw % W_IMG;

    const int cbase = (b * C3 + nh * HD) * HW;
    const float* qb = Q + cbase + hw;
    const float* kb = K + cbase;
    const float* vb = V + cbase;

    float q[HD];
#pragma unroll
    for (int d = 0; d < HD; d++) q[d] = qb[d * HW];

    float m = -1e30f, l = 0.f;
    float acc[HD];
#pragma unroll
    for (int d = 0; d < HD; d++) acc[d] = 0.f;

    for (int i = 0; i < 7; i++) {
        int hh = min(max(h + i - 3, 0), H_IMG - 1);
        for (int j = 0; j < 7; j++) {
            int ww = min(max(w + j - 3, 0), W_IMG - 1);
            int off = hh * W_IMG + ww;
            float s = 0.f;
#pragma unroll
            for (int d = 0; d < HD; d++) s += q[d] * kb[d * HW + off];
            s *= ATT_SCALE;
            float mn = fmaxf(m, s);
            float corr = __expf(m - mn);
            float p    = __expf(s - mn);
            l = l * corr + p;
#pragma unroll
            for (int d = 0; d < HD; d++)
                acc[d] = acc[d] * corr + p * vb[d * HW + off];
            m = mn;
        }
    }
    float inv = 1.f / l;
    float* ob = O + cbase + hw;
#pragma unroll
    for (int d = 0; d < HD; d++) ob[d * HW] = acc[d] * inv;
}

// ---------------- warp-per-pixel LayerNorm over C3=256 (in place, NHWC) --------
__global__ __launch_bounds__(256) void ln_kernel(
    float* __restrict__ X, const float* __restrict__ g, const float* __restrict__ bta,
    int npix)
{
    int wrp  = (blockIdx.x * blockDim.x + threadIdx.x) >> 5;
    int lane = threadIdx.x & 31;
    if (wrp >= npix) return;
    float* xp = X + (long)wrp * C3 + lane * 8;
    float4 v0 = *(float4*)xp;
    float4 v1 = *(float4*)(xp + 4);
    float s  = v0.x + v0.y + v0.z + v0.w + v1.x + v1.y + v1.z + v1.w;
    float ss = v0.x*v0.x + v0.y*v0.y + v0.z*v0.z + v0.w*v0.w
             + v1.x*v1.x + v1.y*v1.y + v1.z*v1.z + v1.w*v1.w;
#pragma unroll
    for (int o = 16; o; o >>= 1) {
        s  += __shfl_xor_sync(0xffffffffu, s,  o);
        ss += __shfl_xor_sync(0xffffffffu, ss, o);
    }
    float mu = s * (1.f / C3);
    float r  = rsqrtf(ss * (1.f / C3) - mu * mu + 1e-5f);
    const float* gp = g   + lane * 8;
    const float* bp = bta + lane * 8;
    float vv[8] = {v0.x, v0.y, v0.z, v0.w, v1.x, v1.y, v1.z, v1.w};
#pragma unroll
    for (int u = 0; u < 8; u++) vv[u] = (vv[u] - mu) * r * gp[u] + bp[u];
    *(float4*)xp       = make_float4(vv[0], vv[1], vv[2], vv[3]);
    *(float4*)(xp + 4) = make_float4(vv[4], vv[5], vv[6], vv[7]);
}

// ---------------- x = LN2(x + y), NHWC -> NCHW transposed output ----------------
__global__ __launch_bounds__(256) void final_kernel(
    const float* __restrict__ X, const float* __restrict__ Y,
    const float* __restrict__ g, const float* __restrict__ bta,
    float* __restrict__ out)
{
    __shared__ float sm[32][264];
    const int b  = blockIdx.y;
    const int p0 = blockIdx.x * 32;
    const int t = threadIdx.x, lane = t & 31, wid = t >> 5;

    for (int qq = 0; qq < 4; qq++) {
        int px = wid * 4 + qq;
        long base = ((long)b * HW + p0 + px) * C3 + lane * 8;
        float4 x0 = *(const float4*)(X + base);
        float4 x1 = *(const float4*)(X + base + 4);
        float4 y0 = *(const float4*)(Y + base);
        float4 y1 = *(const float4*)(Y + base + 4);
        float vv[8] = {x0.x + y0.x, x0.y + y0.y, x0.z + y0.z, x0.w + y0.w,
                       x1.x + y1.x, x1.y + y1.y, x1.z + y1.z, x1.w + y1.w};
        float s = 0.f, ss = 0.f;
#pragma unroll
        for (int u = 0; u < 8; u++) { s += vv[u]; ss += vv[u] * vv[u]; }
#pragma unroll
        for (int o = 16; o; o >>= 1) {
            s  += __shfl_xor_sync(0xffffffffu, s,  o);
            ss += __shfl_xor_sync(0xffffffffu, ss, o);
        }
        float mu = s * (1.f / C3);
        float r  = rsqrtf(ss * (1.f / C3) - mu * mu + 1e-5f);
#pragma unroll
        for (int u = 0; u < 8; u++) {
            int c = lane * 8 + u;
            sm[px][c] = (vv[u] - mu) * r * g[c] + bta[c];
        }
    }
    __syncthreads();
    // coalesced NCHW stores: warp = 32 consecutive pixels of one channel
    int px = t & 31, c0 = t >> 5;
    for (int c = c0; c < C3; c += 8)
        out[((long)b * C3 + c) * HW + p0 + px] = sm[px][c];
}

// ---------------- launch ----------------
extern "C" void kernel_launch(void* const* d_in, const int* in_sizes, int n_in,
                              void* d_out, int out_size)
{
    const float* F_lidar = (const float*)d_in[0];
    const float* F_cam   = (const float*)d_in[1];
    const float* Wq  = (const float*)d_in[2];
    const float* Wk  = (const float*)d_in[3];
    const float* Wv  = (const float*)d_in[4];
    const float* Wo  = (const float*)d_in[5];
    const float* Wr  = (const float*)d_in[6];
    const float* g1  = (const float*)d_in[7];
    const float* b1  = (const float*)d_in[8];
    const float* g2  = (const float*)d_in[9];
    const float* b2  = (const float*)d_in[10];
    const float* W1  = (const float*)d_in[11];
    const float* bf1 = (const float*)d_in[12];
    const float* W2  = (const float*)d_in[13];
    const float* bf2 = (const float*)d_in[14];
    float* out = (float*)d_out;

    float *Q, *K, *V, *AO, *X, *Y, *Hd;
    cudaGetSymbolAddress((void**)&Q,  g_Q);
    cudaGetSymbolAddress((void**)&K,  g_K);
    cudaGetSymbolAddress((void**)&V,  g_V);
    cudaGetSymbolAddress((void**)&AO, g_AO);
    cudaGetSymbolAddress((void**)&X,  g_X);
    cudaGetSymbolAddress((void**)&Y,  g_Y);
    cudaGetSymbolAddress((void**)&Hd, g_Hid);

    dim3 blk(256);
    const long chw = (long)C3 * HW;

    // Q/K/V projections (per-batch GEMMs, weights shared across batch)
    gemm128<false,false,false,false><<<dim3(313,2,BSZ), blk>>>(
        Wq, F_lidar, nullptr, Q, C3, HW, C1, 0, (long)C1*HW, chw);
    gemm128<false,false,false,false><<<dim3(313,2,BSZ), blk>>>(
        Wk, F_cam,   nullptr, K, C3, HW, C3, 0, chw, chw);
    gemm128<false,false,false,false><<<dim3(313,2,BSZ), blk>>>(
        Wv, F_cam,   nullptr, V, C3, HW, C3, 0, chw, chw);

    // local-window attention
    attn_kernel<<<dim3((HW + 255) / 256, NHEADS, BSZ), blk>>>(Q, K, V, AO);

    // out-proj to NHWC, then residual-proj accumulated on top
    gemm128<true,false,false,false><<<dim3(313,2,BSZ), blk>>>(
        Wo, AO,      nullptr, X, C3, HW, C3, 0, chw, chw);
    gemm128<true,true,false,false><<<dim3(313,2,BSZ), blk>>>(
        Wr, F_lidar, nullptr, X, C3, HW, C1, 0, (long)C1*HW, chw);

    // LN1 (in place on NHWC x)
    ln_kernel<<<(BSZ * HW * 32 + 255) / 256, blk>>>(X, g1, b1, BSZ * HW);

    // FFN: hidden = relu(x @ W1 + bf1); y = hidden @ W2 + bf2
    gemm128<false,false,true,true><<<dim3(8,   625, 1), blk>>>(
        X,  W1, bf1, Hd, BSZ * HW, CF, C3, 0, 0, 0);
    gemm128<false,false,false,true><<<dim3(2,  625, 1), blk>>>(
        Hd, W2, bf2, Y,  BSZ * HW, C3, CF, 0, 0, 0);

    // LN2(x + y) and NHWC -> NCHW output
    final_kernel<<<dim3(HW / 32, BSZ), blk>>>(X, Y, g2, b2, out);
}

// round 3
// speedup vs baseline: 2.5204x; 2.5204x over previous
#include <cuda_runtime.h>
#include <math.h>
#include <stdint.h>

#define H_IMG 200
#define W_IMG 200
#define HW    40000
#define C1    64
#define C3    256
#define NHEADS 8
#define HD    32
#define BSZ   2
#define CF    1024
#define ATT_SCALE 0.17677669529663687f   // 32^-0.5

// ---------------- static scratch ----------------
__device__ float g_Q  [BSZ * C3 * HW];   // NCHW
__device__ float g_K  [BSZ * C3 * HW];
__device__ float g_V  [BSZ * C3 * HW];
__device__ float g_AO [BSZ * HW * C3];   // attention output, NHWC
__device__ float g_X  [BSZ * HW * C3];   // NHWC
__device__ float g_Y  [BSZ * HW * C3];   // NHWC
__device__ float g_Hid[BSZ * HW * CF];   // FFN hidden

__device__ __forceinline__ uint32_t f2tf(float x) {
    uint32_t u;
    asm("cvt.rna.tf32.f32 %0, %1;" : "=r"(u) : "f"(x));
    return u;
}

#define SWZ(k, c) ((c) ^ ((((k) >> 2) & 3) << 3))

// ---------------- tf32 tensor-core GEMM ----------------
// C[M,N] = op(A) * op(B).  TA=0: A row-major [M,K]. TA=1: A stored [K,M] (row stride M).
// TB=0: B row-major [K,N]. TB=1: B stored [N,K] (use B^T).
// BM=BN=128, BK=16, 256 threads, 8 warps of 64x32.
template<int TA, int TB, int ACCU, int RELU, int BIAS>
__global__ __launch_bounds__(256) void gemm_tc(
    const float* __restrict__ A, const float* __restrict__ B,
    const float* __restrict__ bias, float* __restrict__ C,
    int M, int N, int K, long aStr, long bStr, long cStr)
{
    __shared__ uint32_t As[2][16][136];
    __shared__ uint32_t Bs[2][16][136];
    A += (long)blockIdx.z * aStr;
    B += (long)blockIdx.z * bStr;
    C += (long)blockIdx.z * cStr;

    const int m0 = blockIdx.y * 128;
    const int n0 = blockIdx.x * 128;
    const int t    = threadIdx.x;
    const int lane = t & 31, w = t >> 5;
    const int g  = lane >> 2, tg = lane & 3;
    const int wmB = (w & 1) * 64, wnB = (w >> 1) * 32;

    float acc[4][4][4];
#pragma unroll
    for (int i = 0; i < 4; i++)
#pragma unroll
        for (int j = 0; j < 4; j++)
#pragma unroll
            for (int r = 0; r < 4; r++) acc[i][j][r] = 0.f;

    float4 ra[2], rb[2];
    const float4 z4 = make_float4(0.f, 0.f, 0.f, 0.f);

    auto loadA = [&](int k0) {
#pragma unroll
        for (int v = 0; v < 2; v++) {
            int f = t + v * 256;
            if (TA == 0) {
                int row = f >> 2, kc = (f & 3) * 4;
                ra[v] = z4;
                if (m0 + row < M)
                    ra[v] = *(const float4*)(A + (long)(m0 + row) * K + k0 + kc);
            } else {
                int krow = f >> 5, mc = (f & 31) * 4;
                ra[v] = z4;
                if (m0 + mc < M)
                    ra[v] = *(const float4*)(A + (long)(k0 + krow) * M + m0 + mc);
            }
        }
    };
    auto loadB = [&](int k0) {
#pragma unroll
        for (int v = 0; v < 2; v++) {
            int f = t + v * 256;
            if (TB == 0) {
                int krow = f >> 5, nc = (f & 31) * 4;
                rb[v] = z4;
                if (n0 + nc < N)
                    rb[v] = *(const float4*)(B + (long)(k0 + krow) * N + n0 + nc);
            } else {
                int nrow = f >> 2, kc = (f & 3) * 4;
                rb[v] = z4;
                if (n0 + nrow < N)
                    rb[v] = *(const float4*)(B + (long)(n0 + nrow) * K + k0 + kc);
            }
        }
    };
    auto storeAB = [&](int buf) {
#pragma unroll
        for (int v = 0; v < 2; v++) {
            int f = t + v * 256;
            float av[4] = {ra[v].x, ra[v].y, ra[v].z, ra[v].w};
            float bv[4] = {rb[v].x, rb[v].y, rb[v].z, rb[v].w};
            if (TA == 0) {
                int row = f >> 2, kc = (f & 3) * 4;
#pragma unroll
                for (int i = 0; i < 4; i++)
                    As[buf][kc + i][SWZ(kc + i, row)] = f2tf(av[i]);
            } else {
                int krow = f >> 5, mc = (f & 31) * 4;
                int c0 = SWZ(krow, mc);
#pragma unroll
                for (int i = 0; i < 4; i++)
                    As[buf][krow][c0 + i] = f2tf(av[i]);
            }
            if (TB == 0) {
                int krow = f >> 5, nc = (f & 31) * 4;
                int c0 = SWZ(krow, nc);
#pragma unroll
                for (int i = 0; i < 4; i++)
                    Bs[buf][krow][c0 + i] = f2tf(bv[i]);
            } else {
                int nrow = f >> 2, kc = (f & 3) * 4;
#pragma unroll
                for (int i = 0; i < 4; i++)
                    Bs[buf][kc + i][SWZ(kc + i, nrow)] = f2tf(bv[i]);
            }
        }
    };
    auto compute = [&](int buf) {
#pragma unroll
        for (int kk = 0; kk < 16; kk += 8) {
            int kA = kk + tg, kB = kk + tg + 4;
            uint32_t bf[4][2];
#pragma unroll
            for (int ns = 0; ns < 4; ns++) {
                int n = wnB + ns * 8 + g;
                bf[ns][0] = Bs[buf][kA][SWZ(kA, n)];
                bf[ns][1] = Bs[buf][kB][SWZ(kB, n)];
            }
#pragma unroll
            for (int ms = 0; ms < 4; ms++) {
                int m = wmB + ms * 16 + g;
                uint32_t a0 = As[buf][kA][SWZ(kA, m)];
                uint32_t a1 = As[buf][kA][SWZ(kA, m + 8)];
                uint32_t a2 = As[buf][kB][SWZ(kB, m)];
                uint32_t a3 = As[buf][kB][SWZ(kB, m + 8)];
#pragma unroll
                for (int ns = 0; ns < 4; ns++) {
                    asm volatile(
                        "mma.sync.aligned.m16n8k8.row.col.f32.tf32.tf32.f32 "
                        "{%0,%1,%2,%3}, {%4,%5,%6,%7}, {%8,%9}, {%0,%1,%2,%3};\n"
                        : "+f"(acc[ms][ns][0]), "+f"(acc[ms][ns][1]),
                          "+f"(acc[ms][ns][2]), "+f"(acc[ms][ns][3])
                        : "r"(a0), "r"(a1), "r"(a2), "r"(a3),
                          "r"(bf[ns][0]), "r"(bf[ns][1]));
                }
            }
        }
    };

    const int ktiles = K >> 4;
    loadA(0); loadB(0);
    storeAB(0);
    __syncthreads();
    for (int kt = 0; kt < ktiles; kt++) {
        int buf = kt & 1;
        if (kt + 1 < ktiles) { loadA((kt + 1) << 4); loadB((kt + 1) << 4); }
        compute(buf);
        if (kt + 1 < ktiles) storeAB(buf ^ 1);
        __syncthreads();
    }

    // epilogue
#pragma unroll
    for (int ms = 0; ms < 4; ms++) {
#pragma unroll
        for (int ns = 0; ns < 4; ns++) {
            int ncol = n0 + wnB + ns * 8 + tg * 2;
            if (ncol >= N) continue;
            int mrow = m0 + wmB + ms * 16 + g;
#pragma unroll
            for (int r = 0; r < 2; r++) {
                int m = mrow + r * 8;
                if (m >= M) continue;
                float v0 = acc[ms][ns][r * 2];
                float v1 = acc[ms][ns][r * 2 + 1];
                if (BIAS) { v0 += bias[ncol]; v1 += bias[ncol + 1]; }
                if (RELU) { v0 = fmaxf(v0, 0.f); v1 = fmaxf(v1, 0.f); }
                float2* p = (float2*)(C + (long)m * N + ncol);
                if (ACCU) { float2 o = *p; v0 += o.x; v1 += o.y; }
                *p = make_float2(v0, v1);
            }
        }
    }
}

// ---------------- 7x7 local-window attention (NCHW in, NHWC out) ----------------
__global__ __launch_bounds__(256) void attn_kernel(
    const float* __restrict__ Q, const float* __restrict__ K,
    const float* __restrict__ V, float* __restrict__ O)
{
    const int b = blockIdx.z, nh = blockIdx.y;
    const int hw = blockIdx.x * blockDim.x + threadIdx.x;
    if (hw >= HW) return;
    const int h = hw / W_IMG, w = hw % W_IMG;

    const int cbase = (b * C3 + nh * HD) * HW;
    const float* qb = Q + cbase + hw;
    const float* kb = K + cbase;
    const float* vb = V + cbase;

    float q[HD];
#pragma unroll
    for (int d = 0; d < HD; d++) q[d] = qb[d * HW];

    float m = -1e30f, l = 0.f;
    float acc[HD];
#pragma unroll
    for (int d = 0; d < HD; d++) acc[d] = 0.f;

    for (int i = 0; i < 7; i++) {
        int hh = min(max(h + i - 3, 0), H_IMG - 1);
        for (int j = 0; j < 7; j++) {
            int ww = min(max(w + j - 3, 0), W_IMG - 1);
            int off = hh * W_IMG + ww;
            float s = 0.f;
#pragma unroll
            for (int d = 0; d < HD; d++) s += q[d] * kb[d * HW + off];
            s *= ATT_SCALE;
            float mn = fmaxf(m, s);
            float corr = __expf(m - mn);
            float p    = __expf(s - mn);
            l = l * corr + p;
#pragma unroll
            for (int d = 0; d < HD; d++)
                acc[d] = acc[d] * corr + p * vb[d * HW + off];
            m = mn;
        }
    }
    float inv = 1.f / l;
    // NHWC output: 32 contiguous floats
    float* ob = O + ((long)(b * HW + hw)) * C3 + nh * HD;
#pragma unroll
    for (int d = 0; d < HD; d += 4) {
        *(float4*)(ob + d) = make_float4(acc[d] * inv, acc[d+1] * inv,
                                         acc[d+2] * inv, acc[d+3] * inv);
    }
}

// ---------------- warp-per-pixel LayerNorm (in place, NHWC) --------
__global__ __launch_bounds__(256) void ln_kernel(
    float* __restrict__ X, const float* __restrict__ g, const float* __restrict__ bta,
    int npix)
{
    int wrp  = (blockIdx.x * blockDim.x + threadIdx.x) >> 5;
    int lane = threadIdx.x & 31;
    if (wrp >= npix) return;
    float* xp = X + (long)wrp * C3 + lane * 8;
    float4 v0 = *(float4*)xp;
    float4 v1 = *(float4*)(xp + 4);
    float s  = v0.x + v0.y + v0.z + v0.w + v1.x + v1.y + v1.z + v1.w;
    float ss = v0.x*v0.x + v0.y*v0.y + v0.z*v0.z + v0.w*v0.w
             + v1.x*v1.x + v1.y*v1.y + v1.z*v1.z + v1.w*v1.w;
#pragma unroll
    for (int o = 16; o; o >>= 1) {
        s  += __shfl_xor_sync(0xffffffffu, s,  o);
        ss += __shfl_xor_sync(0xffffffffu, ss, o);
    }
    float mu = s * (1.f / C3);
    float r  = rsqrtf(ss * (1.f / C3) - mu * mu + 1e-5f);
    const float* gp = g   + lane * 8;
    const float* bp = bta + lane * 8;
    float vv[8] = {v0.x, v0.y, v0.z, v0.w, v1.x, v1.y, v1.z, v1.w};
#pragma unroll
    for (int u = 0; u < 8; u++) vv[u] = (vv[u] - mu) * r * gp[u] + bp[u];
    *(float4*)xp       = make_float4(vv[0], vv[1], vv[2], vv[3]);
    *(float4*)(xp + 4) = make_float4(vv[4], vv[5], vv[6], vv[7]);
}

// ---------------- x = LN2(x + y), NHWC -> NCHW output ----------------
__global__ __launch_bounds__(256) void final_kernel(
    const float* __restrict__ X, const float* __restrict__ Y,
    const float* __restrict__ g, const float* __restrict__ bta,
    float* __restrict__ out)
{
    __shared__ float sm[32][264];
    const int b  = blockIdx.y;
    const int p0 = blockIdx.x * 32;
    const int t = threadIdx.x, lane = t & 31, wid = t >> 5;

    for (int qq = 0; qq < 4; qq++) {
        int px = wid * 4 + qq;
        long base = ((long)b * HW + p0 + px) * C3 + lane * 8;
        float4 x0 = *(const float4*)(X + base);
        float4 x1 = *(const float4*)(X + base + 4);
        float4 y0 = *(const float4*)(Y + base);
        float4 y1 = *(const float4*)(Y + base + 4);
        float vv[8] = {x0.x + y0.x, x0.y + y0.y, x0.z + y0.z, x0.w + y0.w,
                       x1.x + y1.x, x1.y + y1.y, x1.z + y1.z, x1.w + y1.w};
        float s = 0.f, ss = 0.f;
#pragma unroll
        for (int u = 0; u < 8; u++) { s += vv[u]; ss += vv[u] * vv[u]; }
#pragma unroll
        for (int o = 16; o; o >>= 1) {
            s  += __shfl_xor_sync(0xffffffffu, s,  o);
            ss += __shfl_xor_sync(0xffffffffu, ss, o);
        }
        float mu = s * (1.f / C3);
        float r  = rsqrtf(ss * (1.f / C3) - mu * mu + 1e-5f);
#pragma unroll
        for (int u = 0; u < 8; u++) {
            int c = lane * 8 + u;
            sm[px][c] = (vv[u] - mu) * r * g[c] + bta[c];
        }
    }
    __syncthreads();
    int px = t & 31, c0 = t >> 5;
    for (int c = c0; c < C3; c += 8)
        out[((long)b * C3 + c) * HW + p0 + px] = sm[px][c];
}

// ---------------- launch ----------------
extern "C" void kernel_launch(void* const* d_in, const int* in_sizes, int n_in,
                              void* d_out, int out_size)
{
    const float* F_lidar = (const float*)d_in[0];
    const float* F_cam   = (const float*)d_in[1];
    const float* Wq  = (const float*)d_in[2];
    const float* Wk  = (const float*)d_in[3];
    const float* Wv  = (const float*)d_in[4];
    const float* Wo  = (const float*)d_in[5];
    const float* Wr  = (const float*)d_in[6];
    const float* g1  = (const float*)d_in[7];
    const float* b1  = (const float*)d_in[8];
    const float* g2  = (const float*)d_in[9];
    const float* b2  = (const float*)d_in[10];
    const float* W1  = (const float*)d_in[11];
    const float* bf1 = (const float*)d_in[12];
    const float* W2  = (const float*)d_in[13];
    const float* bf2 = (const float*)d_in[14];
    float* out = (float*)d_out;

    float *Q, *K, *V, *AO, *X, *Y, *Hd;
    cudaGetSymbolAddress((void**)&Q,  g_Q);
    cudaGetSymbolAddress((void**)&K,  g_K);
    cudaGetSymbolAddress((void**)&V,  g_V);
    cudaGetSymbolAddress((void**)&AO, g_AO);
    cudaGetSymbolAddress((void**)&X,  g_X);
    cudaGetSymbolAddress((void**)&Y,  g_Y);
    cudaGetSymbolAddress((void**)&Hd, g_Hid);

    dim3 blk(256);
    const long chw  = (long)C3 * HW;      // NCHW batch stride
    const long c1hw = (long)C1 * HW;
    const long xstr = (long)HW * C3;      // NHWC batch stride

    // projections: C[ch][pix] = W @ feat  (NCHW out)
    gemm_tc<0,0,0,0,0><<<dim3(313, 2, BSZ), blk>>>(
        Wq, F_lidar, nullptr, Q, C3, HW, C1, 0, c1hw, chw);
    gemm_tc<0,0,0,0,0><<<dim3(313, 2, BSZ), blk>>>(
        Wk, F_cam, nullptr, K, C3, HW, C3, 0, chw, chw);
    gemm_tc<0,0,0,0,0><<<dim3(313, 2, BSZ), blk>>>(
        Wv, F_cam, nullptr, V, C3, HW, C3, 0, chw, chw);

    // attention (NHWC output)
    attn_kernel<<<dim3((HW + 255) / 256, NHEADS, BSZ), blk>>>(Q, K, V, AO);

    // X = AO @ Wo^T   (one big GEMM over both batches)
    gemm_tc<0,1,0,0,0><<<dim3(2, 625, 1), blk>>>(
        AO, Wo, nullptr, X, BSZ * HW, C3, C3, 0, 0, 0);
    // X += F_lidar^T @ Wr^T  (per batch; A stored [C1][HW])
    gemm_tc<1,1,1,0,0><<<dim3(2, 313, BSZ), blk>>>(
        F_lidar, Wr, nullptr, X, HW, C3, C1, c1hw, 0, xstr);

    // LN1 in place
    ln_kernel<<<(BSZ * HW * 32 + 255) / 256, blk>>>(X, g1, b1, BSZ * HW);

    // FFN
    gemm_tc<0,0,0,1,1><<<dim3(8, 625, 1), blk>>>(
        X,  W1, bf1, Hd, BSZ * HW, CF, C3, 0, 0, 0);
    gemm_tc<0,0,0,0,1><<<dim3(2, 625, 1), blk>>>(
        Hd, W2, bf2, Y,  BSZ * HW, C3, CF, 0, 0, 0);

    // LN2(x+y) -> NCHW
    final_kernel<<<dim3(HW / 32, BSZ), blk>>>(X, Y, g2, b2, out);
}